// round 1
// baseline (speedup 1.0000x reference)
#include <cuda_runtime.h>
#include <math.h>

#define NG 1024
#define HD 128
#define ET 500000
#define NN 100000
#define SQRT_H 11.313708498984761f

#define TE 96      // edges per tile
#define XP 388     // Xs pitch in floats (384 + 4 pad, multiple of 4)
#define EPW 12     // edges per warp (TE / 8 warps)

// ---------------- scratch (device globals; no allocation allowed) ----------------
__device__ unsigned g_tmax[NN];
__device__ float    g_tsum[NN];
__device__ float    g_logits[ET];
__device__ float    g_logpb[NG];
__device__ int      g_selcnt[NG];
__device__ int      g_mask_mode;   // 0=bool/uint8, 1=int32, 2=float32

// ---------------- helpers ----------------
__device__ __forceinline__ float gelu_f(float x){
    return 0.5f * x * (1.0f + erff(x * 0.70710678118654752440f));
}
__device__ __forceinline__ unsigned fenc(float f){
    unsigned b = __float_as_uint(f);
    return (b & 0x80000000u) ? ~b : (b | 0x80000000u);
}
__device__ __forceinline__ float fdec(unsigned u){
    return __uint_as_float((u & 0x80000000u) ? (u & 0x7FFFFFFFu) : ~u);
}
__device__ __forceinline__ float4 ld4(const float* p){ return *(const float4*)p; }
__device__ __forceinline__ void st4(float* p, float4 v){ *(float4*)p = v; }

// block reduction for exactly 128 threads (4 warps)
__device__ __forceinline__ float bsum128(float v, float* red){
    #pragma unroll
    for (int o = 16; o > 0; o >>= 1) v += __shfl_xor_sync(0xFFFFFFFFu, v, o);
    int w = threadIdx.x >> 5;
    if ((threadIdx.x & 31) == 0) red[w] = v;
    __syncthreads();
    if (threadIdx.x == 0) red[0] = red[0] + red[1] + red[2] + red[3];
    __syncthreads();
    float r = red[0];
    __syncthreads();
    return r;
}

// ---------------- init ----------------
__global__ void k_init(){
    int i = blockIdx.x * blockDim.x + threadIdx.x;
    if (i < NN){ g_tmax[i] = 0u; g_tsum[i] = 0.0f; }
    if (i < NG){ g_logpb[i] = 0.0f; g_selcnt[i] = 0; }
}

// detect selected_mask dtype from raw words (deterministic for fixed input)
__global__ void k_detect(const unsigned* __restrict__ m){
    __shared__ int fl;
    if (threadIdx.x == 0) fl = 0;
    __syncthreads();
    int loc = 0;
    for (int i = threadIdx.x; i < 4096; i += blockDim.x){
        unsigned w = m[i];
        if (w == 0x3F800000u) loc |= 1;       // float32 1.0f pattern
        else if (w > 1u)      loc |= 2;       // packed-bool pattern (e.g. 0x00010001)
    }
    atomicOr(&fl, loc);
    __syncthreads();
    if (threadIdx.x == 0)
        g_mask_mode = (fl & 1) ? 2 : ((fl & 2) ? 0 : 1);
}

// ---------------- per-graph: start aggregation + ctx MLP + log_z ----------------
__global__ __launch_bounds__(128) void k_graph(
    const float* __restrict__ node, const float* __restrict__ ques,
    const float* __restrict__ ln1g, const float* __restrict__ ln1b,
    const float* __restrict__ zw1,  const float* __restrict__ zb1,
    const float* __restrict__ zw2,  const float* __restrict__ zb2,
    const float* __restrict__ cw1,  const float* __restrict__ cb1,
    const float* __restrict__ cw2,  const float* __restrict__ cb2,
    const int* __restrict__ locals, const int* __restrict__ ptr,
    float* __restrict__ out)
{
    __shared__ float xs[2 * HD];
    __shared__ float hs[HD];
    __shared__ float red[4];
    __shared__ float sc[32];
    __shared__ int   locs[32];

    int g = blockIdx.x, t = threadIdx.x;
    float q = ques[g * HD + t];
    xs[HD + t] = q;

    int p0 = ptr[g], p1 = ptr[g + 1];
    int cnt = p1 - p0; if (cnt > 32) cnt = 32;

    for (int i = 0; i < cnt; i++){
        int loc = locals[p0 + i];
        if (t == 0) locs[i] = loc;
        float v = node[loc * HD + t];
        float s = bsum128(v * q, red);
        if (t == 0) sc[i] = s / SQRT_H;
    }
    __syncthreads();

    // segment softmax over this graph's starts (every thread computes locally)
    float m = -1e30f;
    for (int i = 0; i < cnt; i++) m = fmaxf(m, sc[i]);
    float den = 0.0f;
    for (int i = 0; i < cnt; i++) den += expf(sc[i] - m);
    float summ = 0.0f;
    for (int i = 0; i < cnt; i++){
        float a = expf(sc[i] - m) / den;
        summ += a * node[locs[i] * HD + t];
    }
    xs[t] = summ;
    __syncthreads();

    // ctx_projector: Linear(256,128) -> GELU -> Linear(128,128)
    float acc = cb1[t];
    #pragma unroll 8
    for (int k = 0; k < 2 * HD; k++) acc += xs[k] * cw1[k * HD + t];
    hs[t] = gelu_f(acc);
    __syncthreads();
    float ctx = cb2[t];
    #pragma unroll 8
    for (int k = 0; k < HD; k++) ctx += hs[k] * cw2[k * HD + t];

    // LN(context) -> Linear(128,128)+GELU -> Linear(128,1)
    float mean = bsum128(ctx, red) * (1.0f / HD);
    float msq  = bsum128(ctx * ctx, red) * (1.0f / HD);
    float rstd = rsqrtf(msq - mean * mean + 1e-5f);
    __syncthreads();
    xs[t] = (ctx - mean) * rstd * ln1g[t] + ln1b[t];
    __syncthreads();
    float a2 = zb1[t];
    #pragma unroll 8
    for (int k = 0; k < HD; k++) a2 += xs[k] * zw1[k * HD + t];
    float h2 = gelu_f(a2);
    float lz = bsum128(h2 * zw2[t], red);
    if (t == 0) out[g * 3 + 0] = lz + zb2[0];
}

// ---------------- edge MLP: gather+LN + [E,384]x[384,128] + GELU + [128]->1 ----------------
__global__ __launch_bounds__(256, 1) void k_edge(
    const float* __restrict__ node, const float* __restrict__ ques,
    const float* __restrict__ etok,
    const float* __restrict__ blng, const float* __restrict__ blnb,
    const float* __restrict__ bw1,  const float* __restrict__ bb1,
    const float* __restrict__ bw2,  const float* __restrict__ bb2,
    const int* __restrict__ ebatch, const int* __restrict__ eidx)
{
    extern __shared__ float sm[];
    float* Xs = sm;                         // TE * XP floats (normalized edge_ctx, [e][k])
    float* Ws = sm + TE * XP;               // 32 * 128 floats (W chunk, [k][j])
    int*  tgt_s = (int*)(Ws + 32 * HD);     // TE ints

    int t = threadIdx.x, lane = t & 31, w = t >> 5;
    int e0 = blockIdx.x * TE;

    // ---- gather + LayerNorm(384) into smem ----
    for (int i = 0; i < EPW; i++){
        int el = w * EPW + i;
        int e  = e0 + el;
        if (e >= ET){ if (lane == 0) tgt_s[el] = 0; continue; }
        int eb = ebatch[e];
        int tg = eidx[ET + e];              // edge_index[1][e]
        if (lane == 0) tgt_s[el] = tg;
        int k = lane * 4;
        float4 a = ld4(etok + (size_t)e  * HD + k);
        float4 b = ld4(ques + (size_t)eb * HD + k);
        float4 c = ld4(node + (size_t)tg * HD + k);
        float s  = a.x+a.y+a.z+a.w + b.x+b.y+b.z+b.w + c.x+c.y+c.z+c.w;
        float ss = a.x*a.x+a.y*a.y+a.z*a.z+a.w*a.w
                 + b.x*b.x+b.y*b.y+b.z*b.z+b.w*b.w
                 + c.x*c.x+c.y*c.y+c.z*c.z+c.w*c.w;
        #pragma unroll
        for (int o = 16; o > 0; o >>= 1){
            s  += __shfl_xor_sync(0xFFFFFFFFu, s,  o);
            ss += __shfl_xor_sync(0xFFFFFFFFu, ss, o);
        }
        float mean = s * (1.0f / 384.0f);
        float rstd = rsqrtf(ss * (1.0f / 384.0f) - mean * mean + 1e-5f);
        float* xr = &Xs[el * XP];
        float4 g0 = ld4(blng + k),       b0 = ld4(blnb + k);
        float4 g1 = ld4(blng + 128 + k), b1 = ld4(blnb + 128 + k);
        float4 g2 = ld4(blng + 256 + k), b2 = ld4(blnb + 256 + k);
        float4 o0, o1, o2;
        o0.x=(a.x-mean)*rstd*g0.x+b0.x; o0.y=(a.y-mean)*rstd*g0.y+b0.y;
        o0.z=(a.z-mean)*rstd*g0.z+b0.z; o0.w=(a.w-mean)*rstd*g0.w+b0.w;
        o1.x=(b.x-mean)*rstd*g1.x+b1.x; o1.y=(b.y-mean)*rstd*g1.y+b1.y;
        o1.z=(b.z-mean)*rstd*g1.z+b1.z; o1.w=(b.w-mean)*rstd*g1.w+b1.w;
        o2.x=(c.x-mean)*rstd*g2.x+b2.x; o2.y=(c.y-mean)*rstd*g2.y+b2.y;
        o2.z=(c.z-mean)*rstd*g2.z+b2.z; o2.w=(c.w-mean)*rstd*g2.w+b2.w;
        st4(xr + k, o0); st4(xr + 128 + k, o1); st4(xr + 256 + k, o2);
    }
    __syncthreads();

    // ---- GEMM: warp owns 12 edges, lane owns 4 output cols; k unrolled by 4 ----
    float acc[EPW][4];
    #pragma unroll
    for (int i = 0; i < EPW; i++){ acc[i][0]=0; acc[i][1]=0; acc[i][2]=0; acc[i][3]=0; }

    float4* Ws4 = (float4*)Ws;
    for (int kc = 0; kc < 12; kc++){
        if (kc > 0) __syncthreads();
        const float4* gw = (const float4*)bw1 + kc * 1024;
        #pragma unroll
        for (int r = 0; r < 4; r++) Ws4[r * 256 + t] = gw[r * 256 + t];
        __syncthreads();
        #pragma unroll
        for (int k4 = 0; k4 < 8; k4++){
            int k = k4 * 4;
            float4 wv0 = Ws4[(k + 0) * 32 + lane];
            float4 wv1 = Ws4[(k + 1) * 32 + lane];
            float4 wv2 = Ws4[(k + 2) * 32 + lane];
            float4 wv3 = Ws4[(k + 3) * 32 + lane];
            #pragma unroll
            for (int i = 0; i < EPW; i++){
                float4 xv = *(const float4*)&Xs[(w * EPW + i) * XP + kc * 32 + k];
                acc[i][0] += xv.x*wv0.x + xv.y*wv1.x + xv.z*wv2.x + xv.w*wv3.x;
                acc[i][1] += xv.x*wv0.y + xv.y*wv1.y + xv.z*wv2.y + xv.w*wv3.y;
                acc[i][2] += xv.x*wv0.z + xv.y*wv1.z + xv.z*wv2.z + xv.w*wv3.z;
                acc[i][3] += xv.x*wv0.w + xv.y*wv1.w + xv.z*wv2.w + xv.w*wv3.w;
            }
        }
    }

    // ---- epilogue: bias + GELU + dot with bw2, warp-reduce per edge ----
    float4 bb = ld4(bb1 + lane * 4);
    float4 w2 = ld4(bw2 + lane * 4);
    float  b2s = bb2[0];
    for (int i = 0; i < EPW; i++){
        float p = gelu_f(acc[i][0] + bb.x) * w2.x
                + gelu_f(acc[i][1] + bb.y) * w2.y
                + gelu_f(acc[i][2] + bb.z) * w2.z
                + gelu_f(acc[i][3] + bb.w) * w2.w;
        #pragma unroll
        for (int o = 16; o > 0; o >>= 1) p += __shfl_xor_sync(0xFFFFFFFFu, p, o);
        if (lane == 0){
            int el = w * EPW + i;
            int e  = e0 + el;
            if (e < ET){
                float lg = p + b2s;
                g_logits[e] = lg;
                atomicMax(&g_tmax[tgt_s[el]], fenc(lg));
            }
        }
    }
}

// ---------------- segment softmax passes ----------------
__global__ void k_pass2(const int* __restrict__ eidx){
    int e = blockIdx.x * blockDim.x + threadIdx.x;
    if (e >= ET) return;
    int tg = eidx[ET + e];
    float sh = g_logits[e] - fdec(g_tmax[tg]);
    g_logits[e] = sh;
    atomicAdd(&g_tsum[tg], expf(sh));
}

__global__ void k_pass3(const int* __restrict__ eidx, const int* __restrict__ ebatch,
                        const void* __restrict__ mask){
    int e = blockIdx.x * blockDim.x + threadIdx.x;
    if (e >= ET) return;
    int mode = g_mask_mode;
    int selv;
    if      (mode == 0) selv = ((const unsigned char*)mask)[e] != 0;
    else if (mode == 1) selv = ((const int*)mask)[e] != 0;
    else                selv = ((const float*)mask)[e] != 0.0f;
    if (!selv) return;
    int tg = eidx[ET + e];
    float lp = g_logits[e] - logf(g_tsum[tg]);
    int gb = ebatch[e];
    atomicAdd(&g_logpb[gb], lp);
    atomicAdd(&g_selcnt[gb], 1);
}

// ---------------- final: per-graph outputs + pb_nll ----------------
__global__ __launch_bounds__(1024) void k_final(float* __restrict__ out){
    __shared__ float rs[32];
    __shared__ int   ri[32];
    int t = threadIdx.x;
    float lp = g_logpb[t];
    int   c  = g_selcnt[t];
    float nll = (c > 0) ? -lp : 0.0f;
    int   has = (c > 0) ? 1 : 0;
    float v = nll; int h = has;
    #pragma unroll
    for (int o = 16; o > 0; o >>= 1){
        v += __shfl_xor_sync(0xFFFFFFFFu, v, o);
        h += __shfl_xor_sync(0xFFFFFFFFu, h, o);
    }
    if ((t & 31) == 0){ rs[t >> 5] = v; ri[t >> 5] = h; }
    __syncthreads();
    if (t < 32){
        float v2 = rs[t]; int h2 = ri[t];
        #pragma unroll
        for (int o = 16; o > 0; o >>= 1){
            v2 += __shfl_xor_sync(0xFFFFFFFFu, v2, o);
            h2 += __shfl_xor_sync(0xFFFFFFFFu, h2, o);
        }
        if (t == 0){ rs[0] = v2; ri[0] = h2; }
    }
    __syncthreads();
    float pbn = rs[0] / fmaxf((float)ri[0], 1.0f);
    out[t * 3 + 1] = lp;
    out[t * 3 + 2] = pbn;
}

// ---------------- launch ----------------
extern "C" void kernel_launch(void* const* d_in, const int* in_sizes, int n_in,
                              void* d_out, int out_size)
{
    // Input-order detection: setup_inputs dict order has start_node_locals (4096)
    // at index 3; reference-signature order has ln1_g (128) there.
    int iN, iQ, iE, iLN1G, iLN1B, iZW1, iZB1, iZW2, iZB2,
        iCW1, iCB1, iCW2, iCB2, iBLG, iBLB, iBW1, iBB1, iBW2, iBB2,
        iLOC, iPTR, iEB, iMASK, iEIDX;
    if (in_sizes[3] == 4096){
        // dict order
        iN=0; iQ=1; iE=2; iLOC=3; iPTR=4; iEB=5; iMASK=6; iEIDX=7;
        iLN1G=8; iLN1B=9; iZW1=10; iZB1=11; iZW2=12; iZB2=13;
        iCW1=14; iCB1=15; iCW2=16; iCB2=17;
        iBLG=18; iBLB=19; iBW1=20; iBB1=21; iBW2=22; iBB2=23;
    } else {
        // signature order
        iN=0; iQ=1; iE=2;
        iLN1G=3; iLN1B=4; iZW1=5; iZB1=6; iZW2=7; iZB2=8;
        iCW1=9; iCB1=10; iCW2=11; iCB2=12;
        iBLG=13; iBLB=14; iBW1=15; iBB1=16; iBW2=17; iBB2=18;
        iLOC=19; iPTR=20; iEB=21; iMASK=22; iEIDX=23;
    }

    const float* node = (const float*)d_in[iN];
    const float* ques = (const float*)d_in[iQ];
    const float* etok = (const float*)d_in[iE];
    const float* ln1g = (const float*)d_in[iLN1G];
    const float* ln1b = (const float*)d_in[iLN1B];
    const float* zw1  = (const float*)d_in[iZW1];
    const float* zb1  = (const float*)d_in[iZB1];
    const float* zw2  = (const float*)d_in[iZW2];
    const float* zb2  = (const float*)d_in[iZB2];
    const float* cw1  = (const float*)d_in[iCW1];
    const float* cb1  = (const float*)d_in[iCB1];
    const float* cw2  = (const float*)d_in[iCW2];
    const float* cb2  = (const float*)d_in[iCB2];
    const float* blng = (const float*)d_in[iBLG];
    const float* blnb = (const float*)d_in[iBLB];
    const float* bw1  = (const float*)d_in[iBW1];
    const float* bb1  = (const float*)d_in[iBB1];
    const float* bw2  = (const float*)d_in[iBW2];
    const float* bb2  = (const float*)d_in[iBB2];
    const int* locals = (const int*)d_in[iLOC];
    const int* ptr    = (const int*)d_in[iPTR];
    const int* ebatch = (const int*)d_in[iEB];
    const void* mask  = (const void*)d_in[iMASK];
    const int* eidx   = (const int*)d_in[iEIDX];
    float* out = (float*)d_out;

    const int SMEM_EDGE = (TE * XP + 32 * HD) * 4 + TE * 4;   // ~162 KB
    cudaFuncSetAttribute(k_edge, cudaFuncAttributeMaxDynamicSharedMemorySize, SMEM_EDGE);

    k_init<<<(NN + 255) / 256, 256>>>();
    k_detect<<<1, 256>>>((const unsigned*)mask);
    k_graph<<<NG, 128>>>(node, ques, ln1g, ln1b, zw1, zb1, zw2, zb2,
                         cw1, cb1, cw2, cb2, locals, ptr, out);
    k_edge<<<(ET + TE - 1) / TE, 256, SMEM_EDGE>>>(node, ques, etok, blng, blnb,
                                                   bw1, bb1, bw2, bb2, ebatch, eidx);
    k_pass2<<<(ET + 255) / 256, 256>>>(eidx);
    k_pass3<<<(ET + 255) / 256, 256>>>(eidx, ebatch, mask);
    k_final<<<1, 1024>>>(out);
}

// round 3
// speedup vs baseline: 3.0755x; 3.0755x over previous
#include <cuda_runtime.h>
#include <cuda_bf16.h>
#include <math.h>
#include <stdint.h>

#define NG 1024
#define HD 128
#define ET 500000
#define NN 100000
#define SQRT_H 11.313708498984761f

#define TM 128                 // edges per CTA
#define KD 384                 // 3*H
#define KP 392                 // padded A row pitch (bf16 elems)
#define NKS 24                 // K16 steps

// ---------------- scratch (device globals; no allocation allowed) ----------------
__device__ unsigned g_tmax[NN];
__device__ float    g_tsum[NN];
__device__ float    g_logits[ET];
__device__ float    g_logpb[NG];
__device__ int      g_selcnt[NG];
__device__ int      g_mask_mode;   // 0=bool/uint8, 1=int32, 2=float32
// W1 in HMMA B-fragment order: [kstep(24)][ntile(16)][lane(32)] two b32 planes
__device__ __align__(16) unsigned g_Bf0[NKS * 16 * 32];
__device__ __align__(16) unsigned g_Bf1[NKS * 16 * 32];

// ---------------- helpers ----------------
__device__ __forceinline__ float gelu_f(float x){
    return 0.5f * x * (1.0f + erff(x * 0.70710678118654752440f));
}
__device__ __forceinline__ unsigned fenc(float f){
    unsigned b = __float_as_uint(f);
    return (b & 0x80000000u) ? ~b : (b | 0x80000000u);
}
__device__ __forceinline__ float fdec(unsigned u){
    return __uint_as_float((u & 0x80000000u) ? (u & 0x7FFFFFFFu) : ~u);
}
__device__ __forceinline__ float4 ld4(const float* p){ return *(const float4*)p; }

__device__ __forceinline__ uint32_t smem_u32(const void* p){
    uint32_t a;
    asm("{ .reg .u64 t; cvta.to.shared.u64 t, %1; cvt.u32.u64 %0, t; }" : "=r"(a) : "l"(p));
    return a;
}
__device__ __forceinline__ unsigned packbf2(float lo, float hi){
    __nv_bfloat162 v;
    v.x = __float2bfloat16(lo);
    v.y = __float2bfloat16(hi);
    return *(unsigned*)&v;
}
__device__ __forceinline__ void ldm_x4(uint32_t* r, uint32_t addr){
    asm volatile("ldmatrix.sync.aligned.m8n8.x4.shared.b16 {%0,%1,%2,%3}, [%4];"
                 : "=r"(r[0]), "=r"(r[1]), "=r"(r[2]), "=r"(r[3]) : "r"(addr));
}
__device__ __forceinline__ void mma16816(float* d, const uint32_t* a,
                                         uint32_t b0, uint32_t b1){
    asm volatile(
        "mma.sync.aligned.m16n8k16.row.col.f32.bf16.bf16.f32 "
        "{%0,%1,%2,%3}, {%4,%5,%6,%7}, {%8,%9}, {%0,%1,%2,%3};"
        : "+f"(d[0]), "+f"(d[1]), "+f"(d[2]), "+f"(d[3])
        : "r"(a[0]), "r"(a[1]), "r"(a[2]), "r"(a[3]), "r"(b0), "r"(b1));
}

// block reduction for exactly 128 threads (4 warps)
__device__ __forceinline__ float bsum128(float v, float* red){
    #pragma unroll
    for (int o = 16; o > 0; o >>= 1) v += __shfl_xor_sync(0xFFFFFFFFu, v, o);
    int w = threadIdx.x >> 5;
    if ((threadIdx.x & 31) == 0) red[w] = v;
    __syncthreads();
    if (threadIdx.x == 0) red[0] = red[0] + red[1] + red[2] + red[3];
    __syncthreads();
    float r = red[0];
    __syncthreads();
    return r;
}

// ---------------- init ----------------
__global__ void k_init(){
    int i = blockIdx.x * blockDim.x + threadIdx.x;
    if (i < NN){ g_tmax[i] = 0u; g_tsum[i] = 0.0f; }
    if (i < NG){ g_logpb[i] = 0.0f; g_selcnt[i] = 0; }
}

// detect selected_mask dtype from raw words
__global__ void k_detect(const unsigned* __restrict__ m){
    __shared__ int fl;
    if (threadIdx.x == 0) fl = 0;
    __syncthreads();
    int loc = 0;
    for (int i = threadIdx.x; i < 4096; i += blockDim.x){
        unsigned w = m[i];
        if (w == 0x3F800000u) loc |= 1;
        else if (w > 1u)      loc |= 2;
    }
    atomicOr(&fl, loc);
    __syncthreads();
    if (threadIdx.x == 0)
        g_mask_mode = (fl & 1) ? 2 : ((fl & 2) ? 0 : 1);
}

// ---------------- W1 -> HMMA B-fragment order (bf16) ----------------
// b0 plane: {w[k0][n], w[k0+1][n]}   b1 plane: {w[k0+8][n], w[k0+9][n]}
// with n = nt*8 + (lane>>2), k0 = s*16 + (lane&3)*2
__global__ void k_bprep(const float* __restrict__ bw1){
    int i = blockIdx.x * blockDim.x + threadIdx.x;
    if (i >= NKS * 16 * 32) return;
    int lane = i & 31, nt = (i >> 5) & 15, s = i >> 9;
    int n  = nt * 8 + (lane >> 2);
    int k0 = s * 16 + (lane & 3) * 2;
    g_Bf0[i] = packbf2(bw1[k0 * HD + n],       bw1[(k0 + 1) * HD + n]);
    g_Bf1[i] = packbf2(bw1[(k0 + 8) * HD + n], bw1[(k0 + 9) * HD + n]);
}

// ---------------- per-graph: start aggregation + ctx MLP + log_z ----------------
__global__ __launch_bounds__(128) void k_graph(
    const float* __restrict__ node, const float* __restrict__ ques,
    const float* __restrict__ ln1g, const float* __restrict__ ln1b,
    const float* __restrict__ zw1,  const float* __restrict__ zb1,
    const float* __restrict__ zw2,  const float* __restrict__ zb2,
    const float* __restrict__ cw1,  const float* __restrict__ cb1,
    const float* __restrict__ cw2,  const float* __restrict__ cb2,
    const int* __restrict__ locals, const int* __restrict__ ptr,
    float* __restrict__ out)
{
    __shared__ float xs[2 * HD];
    __shared__ float hs[HD];
    __shared__ float red[4];
    __shared__ float sc[32];
    __shared__ int   locs[32];

    int g = blockIdx.x, t = threadIdx.x;
    float q = ques[g * HD + t];
    xs[HD + t] = q;

    int p0 = ptr[g], p1 = ptr[g + 1];
    int cnt = p1 - p0; if (cnt > 32) cnt = 32;

    for (int i = 0; i < cnt; i++){
        int loc = locals[p0 + i];
        if (t == 0) locs[i] = loc;
        float v = node[loc * HD + t];
        float s = bsum128(v * q, red);
        if (t == 0) sc[i] = s / SQRT_H;
    }
    __syncthreads();

    float m = -1e30f;
    for (int i = 0; i < cnt; i++) m = fmaxf(m, sc[i]);
    float den = 0.0f;
    for (int i = 0; i < cnt; i++) den += expf(sc[i] - m);
    float summ = 0.0f;
    for (int i = 0; i < cnt; i++){
        float a = expf(sc[i] - m) / den;
        summ += a * node[locs[i] * HD + t];
    }
    xs[t] = summ;
    __syncthreads();

    float acc = cb1[t];
    #pragma unroll 8
    for (int k = 0; k < 2 * HD; k++) acc += xs[k] * cw1[k * HD + t];
    hs[t] = gelu_f(acc);
    __syncthreads();
    float ctx = cb2[t];
    #pragma unroll 8
    for (int k = 0; k < HD; k++) ctx += hs[k] * cw2[k * HD + t];

    float mean = bsum128(ctx, red) * (1.0f / HD);
    float msq  = bsum128(ctx * ctx, red) * (1.0f / HD);
    float rstd = rsqrtf(msq - mean * mean + 1e-5f);
    __syncthreads();
    xs[t] = (ctx - mean) * rstd * ln1g[t] + ln1b[t];
    __syncthreads();
    float a2 = zb1[t];
    #pragma unroll 8
    for (int k = 0; k < HD; k++) a2 += xs[k] * zw1[k * HD + t];
    float h2 = gelu_f(a2);
    float lz = bsum128(h2 * zw2[t], red);
    if (t == 0) out[g * 3 + 0] = lz + zb2[0];
}

// ---------------- edge MLP via bf16 HMMA (mma.sync m16n8k16) ----------------
// dyn smem: A[128][392] bf16 (100352) | Bs0 (49152) | Bs1 (49152)
//         | sBias 512 | sW2 512 | tgt 512 | part 1024   => 201216 B
#define OFF_A    0
#define OFF_B0   100352
#define OFF_B1   149504
#define OFF_BIAS 198656
#define OFF_W2   199168
#define OFF_TGT  199680
#define OFF_PART 200192
#define EDGE_SMEM 201216

__global__ __launch_bounds__(256, 1) void k_edge_mma(
    const float* __restrict__ node, const float* __restrict__ ques,
    const float* __restrict__ etok,
    const float* __restrict__ blng, const float* __restrict__ blnb,
    const float* __restrict__ bb1,  const float* __restrict__ bw2,
    const float* __restrict__ bb2,
    const int* __restrict__ ebatch, const int* __restrict__ eidx)
{
    extern __shared__ char sm[];
    __nv_bfloat16* As = (__nv_bfloat16*)(sm + OFF_A);
    uint32_t* Bs0 = (uint32_t*)(sm + OFF_B0);
    uint32_t* Bs1 = (uint32_t*)(sm + OFF_B1);
    float* sBias  = (float*)(sm + OFF_BIAS);
    float* sW2    = (float*)(sm + OFF_W2);
    int*   tgt_s  = (int*)(sm + OFF_TGT);
    float* part   = (float*)(sm + OFF_PART);   // [2][128]

    int t = threadIdx.x, lane = t & 31, w = t >> 5;
    int gid = lane >> 2, tig = lane & 3;
    int e0 = blockIdx.x * TM;

    // ---- stage B fragments + bias/w2 ----
    {
        uint4* d0 = (uint4*)Bs0; const uint4* s0 = (const uint4*)g_Bf0;
        uint4* d1 = (uint4*)Bs1; const uint4* s1 = (const uint4*)g_Bf1;
        #pragma unroll
        for (int i = 0; i < 12; i++){ d0[i * 256 + t] = s0[i * 256 + t]; }
        #pragma unroll
        for (int i = 0; i < 12; i++){ d1[i * 256 + t] = s1[i * 256 + t]; }
        if (t < HD){ sBias[t] = bb1[t]; sW2[t] = bw2[t]; }
    }

    // ---- A: gather + LayerNorm(384) -> bf16 row-major padded ----
    for (int i = 0; i < 16; i++){
        int el = w * 16 + i;
        int e  = e0 + el;
        int k  = lane * 4;
        __nv_bfloat16* xr = As + el * KP;
        if (e >= ET){
            if (lane == 0) tgt_s[el] = 0;
            *(unsigned*)(xr + k) = 0;       *(unsigned*)(xr + k + 2) = 0;
            *(unsigned*)(xr + 128 + k) = 0; *(unsigned*)(xr + 128 + k + 2) = 0;
            *(unsigned*)(xr + 256 + k) = 0; *(unsigned*)(xr + 256 + k + 2) = 0;
            continue;
        }
        int eb = ebatch[e];
        int tg = eidx[ET + e];
        if (lane == 0) tgt_s[el] = tg;
        float4 a = ld4(etok + (size_t)e  * HD + k);
        float4 b = ld4(ques + (size_t)eb * HD + k);
        float4 c = ld4(node + (size_t)tg * HD + k);
        float s  = a.x+a.y+a.z+a.w + b.x+b.y+b.z+b.w + c.x+c.y+c.z+c.w;
        float ss = a.x*a.x+a.y*a.y+a.z*a.z+a.w*a.w
                 + b.x*b.x+b.y*b.y+b.z*b.z+b.w*b.w
                 + c.x*c.x+c.y*c.y+c.z*c.z+c.w*c.w;
        #pragma unroll
        for (int o = 16; o > 0; o >>= 1){
            s  += __shfl_xor_sync(0xFFFFFFFFu, s,  o);
            ss += __shfl_xor_sync(0xFFFFFFFFu, ss, o);
        }
        float mean = s * (1.0f / 384.0f);
        float rstd = rsqrtf(ss * (1.0f / 384.0f) - mean * mean + 1e-5f);
        float4 g0 = ld4(blng + k),       q0 = ld4(blnb + k);
        float4 g1 = ld4(blng + 128 + k), q1 = ld4(blnb + 128 + k);
        float4 g2 = ld4(blng + 256 + k), q2 = ld4(blnb + 256 + k);
        *(unsigned*)(xr + k)           = packbf2((a.x-mean)*rstd*g0.x+q0.x, (a.y-mean)*rstd*g0.y+q0.y);
        *(unsigned*)(xr + k + 2)       = packbf2((a.z-mean)*rstd*g0.z+q0.z, (a.w-mean)*rstd*g0.w+q0.w);
        *(unsigned*)(xr + 128 + k)     = packbf2((b.x-mean)*rstd*g1.x+q1.x, (b.y-mean)*rstd*g1.y+q1.y);
        *(unsigned*)(xr + 128 + k + 2) = packbf2((b.z-mean)*rstd*g1.z+q1.z, (b.w-mean)*rstd*g1.w+q1.w);
        *(unsigned*)(xr + 256 + k)     = packbf2((c.x-mean)*rstd*g2.x+q2.x, (c.y-mean)*rstd*g2.y+q2.y);
        *(unsigned*)(xr + 256 + k + 2) = packbf2((c.z-mean)*rstd*g2.z+q2.z, (c.w-mean)*rstd*g2.w+q2.w);
    }
    __syncthreads();

    // ---- HMMA mainloop: warp tile 32(M) x 64(N) ----
    int mbase = (w & 3) * 32;        // warp's M block
    int nbt   = (w >> 2) * 8;        // warp's first n-tile (of 8)
    float acc[2][8][4];
    #pragma unroll
    for (int mt = 0; mt < 2; mt++)
        #pragma unroll
        for (int j = 0; j < 8; j++)
            #pragma unroll
            for (int r = 0; r < 4; r++) acc[mt][j][r] = 0.0f;

    uint32_t As_u = smem_u32(As);
    int arow = mbase + (lane & 15);
    int acol = (lane >> 4) * 8;

    for (int s = 0; s < NKS; s++){
        uint32_t a0[4], a1[4];
        uint32_t ad = As_u + (uint32_t)((arow * KP + s * 16 + acol) * 2);
        ldm_x4(a0, ad);
        ldm_x4(a1, ad + (uint32_t)(16 * KP * 2));
        const uint32_t* b0p = Bs0 + (s * 16 + nbt) * 32 + lane;
        const uint32_t* b1p = Bs1 + (s * 16 + nbt) * 32 + lane;
        #pragma unroll
        for (int j = 0; j < 8; j++){
            uint32_t b0 = b0p[j * 32];
            uint32_t b1 = b1p[j * 32];
            mma16816(acc[0][j], a0, b0, b1);
            mma16816(acc[1][j], a1, b0, b1);
        }
    }

    // ---- epilogue: bias + GELU + dot(w2), reduce over lane group ----
    #pragma unroll
    for (int mt = 0; mt < 2; mt++){
        float p0 = 0.0f, p1 = 0.0f;
        #pragma unroll
        for (int j = 0; j < 8; j++){
            int n0 = (nbt + j) * 8 + tig * 2;
            float bia0 = sBias[n0], bia1 = sBias[n0 + 1];
            float w20 = sW2[n0],    w21 = sW2[n0 + 1];
            p0 += gelu_f(acc[mt][j][0] + bia0) * w20 + gelu_f(acc[mt][j][1] + bia1) * w21;
            p1 += gelu_f(acc[mt][j][2] + bia0) * w20 + gelu_f(acc[mt][j][3] + bia1) * w21;
        }
        p0 += __shfl_xor_sync(0xFFFFFFFFu, p0, 1);
        p0 += __shfl_xor_sync(0xFFFFFFFFu, p0, 2);
        p1 += __shfl_xor_sync(0xFFFFFFFFu, p1, 1);
        p1 += __shfl_xor_sync(0xFFFFFFFFu, p1, 2);
        if (tig == 0){
            int r = mbase + mt * 16 + gid;
            part[(w >> 2) * TM + r]     = p0;
            part[(w >> 2) * TM + r + 8] = p1;
        }
    }
    __syncthreads();

    if (w < 4){
        int el = w * 32 + lane;
        int e  = e0 + el;
        if (e < ET){
            float lg = part[el] + part[TM + el] + bb2[0];
            g_logits[e] = lg;
            atomicMax(&g_tmax[tgt_s[el]], fenc(lg));
        }
    }
}

// ---------------- segment softmax passes ----------------
__global__ void k_pass2(const int* __restrict__ eidx){
    int e = blockIdx.x * blockDim.x + threadIdx.x;
    if (e >= ET) return;
    int tg = eidx[ET + e];
    float sh = g_logits[e] - fdec(g_tmax[tg]);
    g_logits[e] = sh;
    atomicAdd(&g_tsum[tg], expf(sh));
}

__global__ void k_pass3(const int* __restrict__ eidx, const int* __restrict__ ebatch,
                        const void* __restrict__ mask){
    int e = blockIdx.x * blockDim.x + threadIdx.x;
    if (e >= ET) return;
    int mode = g_mask_mode;
    int selv;
    if      (mode == 0) selv = ((const unsigned char*)mask)[e] != 0;
    else if (mode == 1) selv = ((const int*)mask)[e] != 0;
    else                selv = ((const float*)mask)[e] != 0.0f;
    if (!selv) return;
    int tg = eidx[ET + e];
    float lp = g_logits[e] - logf(g_tsum[tg]);
    int gb = ebatch[e];
    atomicAdd(&g_logpb[gb], lp);
    atomicAdd(&g_selcnt[gb], 1);
}

// ---------------- final ----------------
__global__ __launch_bounds__(1024) void k_final(float* __restrict__ out){
    __shared__ float rs[32];
    __shared__ int   ri[32];
    int t = threadIdx.x;
    float lp = g_logpb[t];
    int   c  = g_selcnt[t];
    float v = (c > 0) ? -lp : 0.0f;
    int   h = (c > 0) ? 1 : 0;
    #pragma unroll
    for (int o = 16; o > 0; o >>= 1){
        v += __shfl_xor_sync(0xFFFFFFFFu, v, o);
        h += __shfl_xor_sync(0xFFFFFFFFu, h, o);
    }
    if ((t & 31) == 0){ rs[t >> 5] = v; ri[t >> 5] = h; }
    __syncthreads();
    if (t < 32){
        float v2 = rs[t]; int h2 = ri[t];
        #pragma unroll
        for (int o = 16; o > 0; o >>= 1){
            v2 += __shfl_xor_sync(0xFFFFFFFFu, v2, o);
            h2 += __shfl_xor_sync(0xFFFFFFFFu, h2, o);
        }
        if (t == 0){ rs[0] = v2; ri[0] = h2; }
    }
    __syncthreads();
    float pbn = rs[0] / fmaxf((float)ri[0], 1.0f);
    out[t * 3 + 1] = lp;
    out[t * 3 + 2] = pbn;
}

// ---------------- launch ----------------
extern "C" void kernel_launch(void* const* d_in, const int* in_sizes, int n_in,
                              void* d_out, int out_size)
{
    int iN, iQ, iE, iLN1G, iLN1B, iZW1, iZB1, iZW2, iZB2,
        iCW1, iCB1, iCW2, iCB2, iBLG, iBLB, iBW1, iBB1, iBW2, iBB2,
        iLOC, iPTR, iEB, iMASK, iEIDX;
    if (in_sizes[3] == 4096){
        iN=0; iQ=1; iE=2; iLOC=3; iPTR=4; iEB=5; iMASK=6; iEIDX=7;
        iLN1G=8; iLN1B=9; iZW1=10; iZB1=11; iZW2=12; iZB2=13;
        iCW1=14; iCB1=15; iCW2=16; iCB2=17;
        iBLG=18; iBLB=19; iBW1=20; iBB1=21; iBW2=22; iBB2=23;
    } else {
        iN=0; iQ=1; iE=2;
        iLN1G=3; iLN1B=4; iZW1=5; iZB1=6; iZW2=7; iZB2=8;
        iCW1=9; iCB1=10; iCW2=11; iCB2=12;
        iBLG=13; iBLB=14; iBW1=15; iBB1=16; iBW2=17; iBB2=18;
        iLOC=19; iPTR=20; iEB=21; iMASK=22; iEIDX=23;
    }

    const float* node = (const float*)d_in[iN];
    const float* ques = (const float*)d_in[iQ];
    const float* etok = (const float*)d_in[iE];
    const float* ln1g = (const float*)d_in[iLN1G];
    const float* ln1b = (const float*)d_in[iLN1B];
    const float* zw1  = (const float*)d_in[iZW1];
    const float* zb1  = (const float*)d_in[iZB1];
    const float* zw2  = (const float*)d_in[iZW2];
    const float* zb2  = (const float*)d_in[iZB2];
    const float* cw1  = (const float*)d_in[iCW1];
    const float* cb1  = (const float*)d_in[iCB1];
    const float* cw2  = (const float*)d_in[iCW2];
    const float* cb2  = (const float*)d_in[iCB2];
    const float* blng = (const float*)d_in[iBLG];
    const float* blnb = (const float*)d_in[iBLB];
    const float* bw1  = (const float*)d_in[iBW1];
    const float* bb1  = (const float*)d_in[iBB1];
    const float* bw2  = (const float*)d_in[iBW2];
    const float* bb2  = (const float*)d_in[iBB2];
    const int* locals = (const int*)d_in[iLOC];
    const int* ptr    = (const int*)d_in[iPTR];
    const int* ebatch = (const int*)d_in[iEB];
    const void* mask  = (const void*)d_in[iMASK];
    const int* eidx   = (const int*)d_in[iEIDX];
    float* out = (float*)d_out;

    cudaFuncSetAttribute(k_edge_mma, cudaFuncAttributeMaxDynamicSharedMemorySize, EDGE_SMEM);

    k_init<<<(NN + 255) / 256, 256>>>();
    k_detect<<<1, 256>>>((const unsigned*)mask);
    k_bprep<<<(NKS * 16 * 32 + 255) / 256, 256>>>(bw1);
    k_graph<<<NG, 128>>>(node, ques, ln1g, ln1b, zw1, zb1, zw2, zb2,
                         cw1, cb1, cw2, cb2, locals, ptr, out);
    k_edge_mma<<<(ET + TM - 1) / TM, 256, EDGE_SMEM>>>(node, ques, etok, blng, blnb,
                                                       bb1, bw2, bb2, ebatch, eidx);
    k_pass2<<<(ET + 255) / 256, 256>>>(eidx);
    k_pass3<<<(ET + 255) / 256, 256>>>(eidx, ebatch, mask);
    k_final<<<1, 1024>>>(out);
}

// round 4
// speedup vs baseline: 4.6192x; 1.5019x over previous
#include <cuda_runtime.h>
#include <cuda_bf16.h>
#include <math.h>
#include <stdint.h>

#define NG 1024
#define HD 128
#define ET 500000
#define NN 100000
#define SQRT_H 11.313708498984761f

#define TM 128                 // edges per CTA
#define KD 384                 // 3*H
#define KP 392                 // padded A row pitch (bf16 elems)
#define NKS 24                 // K16 steps

// ---------------- scratch (device globals; no allocation allowed) ----------------
__device__ unsigned g_tmax[NN];
__device__ float    g_tsum[NN];
__device__ float    g_logits[ET];
__device__ float    g_logpb[NG];
__device__ int      g_selcnt[NG];
__device__ int      g_mask_mode;   // 0=bool/uint8, 1=int32, 2=float32
// W1 HMMA B-fragments, quad-packed for LDG.128:
// word index = s*512 + (nt>>2)*128 + lane*4 + (nt&3)
__device__ __align__(16) unsigned g_Bf0[NKS * 16 * 32];
__device__ __align__(16) unsigned g_Bf1[NKS * 16 * 32];

// ---------------- helpers ----------------
__device__ __forceinline__ float gelu_f(float x){
    return 0.5f * x * (1.0f + erff(x * 0.70710678118654752440f));
}
__device__ __forceinline__ unsigned fenc(float f){
    unsigned b = __float_as_uint(f);
    return (b & 0x80000000u) ? ~b : (b | 0x80000000u);
}
__device__ __forceinline__ float fdec(unsigned u){
    return __uint_as_float((u & 0x80000000u) ? (u & 0x7FFFFFFFu) : ~u);
}
__device__ __forceinline__ float4 ld4(const float* p){ return *(const float4*)p; }

__device__ __forceinline__ uint32_t smem_u32(const void* p){
    uint32_t a;
    asm("{ .reg .u64 t; cvta.to.shared.u64 t, %1; cvt.u32.u64 %0, t; }" : "=r"(a) : "l"(p));
    return a;
}
__device__ __forceinline__ unsigned packbf2(float lo, float hi){
    __nv_bfloat162 v;
    v.x = __float2bfloat16(lo);
    v.y = __float2bfloat16(hi);
    return *(unsigned*)&v;
}
__device__ __forceinline__ void ldm_x4(uint32_t* r, uint32_t addr){
    asm volatile("ldmatrix.sync.aligned.m8n8.x4.shared.b16 {%0,%1,%2,%3}, [%4];"
                 : "=r"(r[0]), "=r"(r[1]), "=r"(r[2]), "=r"(r[3]) : "r"(addr));
}
__device__ __forceinline__ void mma16816(float* d, const uint32_t* a,
                                         uint32_t b0, uint32_t b1){
    asm volatile(
        "mma.sync.aligned.m16n8k16.row.col.f32.bf16.bf16.f32 "
        "{%0,%1,%2,%3}, {%4,%5,%6,%7}, {%8,%9}, {%0,%1,%2,%3};"
        : "+f"(d[0]), "+f"(d[1]), "+f"(d[2]), "+f"(d[3])
        : "r"(a[0]), "r"(a[1]), "r"(a[2]), "r"(a[3]), "r"(b0), "r"(b1));
}

// block reduction for exactly 128 threads (4 warps)
__device__ __forceinline__ float bsum128(float v, float* red){
    #pragma unroll
    for (int o = 16; o > 0; o >>= 1) v += __shfl_xor_sync(0xFFFFFFFFu, v, o);
    int w = threadIdx.x >> 5;
    if ((threadIdx.x & 31) == 0) red[w] = v;
    __syncthreads();
    if (threadIdx.x == 0) red[0] = red[0] + red[1] + red[2] + red[3];
    __syncthreads();
    float r = red[0];
    __syncthreads();
    return r;
}

// ---------------- init ----------------
__global__ void k_init(){
    int i = blockIdx.x * blockDim.x + threadIdx.x;
    if (i < NN){ g_tmax[i] = 0u; g_tsum[i] = 0.0f; }
    if (i < NG){ g_logpb[i] = 0.0f; g_selcnt[i] = 0; }
}

// detect selected_mask dtype from raw words
__global__ void k_detect(const unsigned* __restrict__ m){
    __shared__ int fl;
    if (threadIdx.x == 0) fl = 0;
    __syncthreads();
    int loc = 0;
    for (int i = threadIdx.x; i < 4096; i += blockDim.x){
        unsigned w = m[i];
        if (w == 0x3F800000u) loc |= 1;
        else if (w > 1u)      loc |= 2;
    }
    atomicOr(&fl, loc);
    __syncthreads();
    if (threadIdx.x == 0)
        g_mask_mode = (fl & 1) ? 2 : ((fl & 2) ? 0 : 1);
}

// ---------------- W1 -> HMMA B-fragment order (bf16), quad-packed ----------------
__global__ void k_bprep(const float* __restrict__ bw1){
    int i = blockIdx.x * blockDim.x + threadIdx.x;
    if (i >= NKS * 16 * 32) return;
    int lane = i & 31, nt = (i >> 5) & 15, s = i >> 9;
    int n  = nt * 8 + (lane >> 2);
    int k0 = s * 16 + (lane & 3) * 2;
    int o  = s * 512 + (nt >> 2) * 128 + lane * 4 + (nt & 3);
    g_Bf0[o] = packbf2(bw1[k0 * HD + n],       bw1[(k0 + 1) * HD + n]);
    g_Bf1[o] = packbf2(bw1[(k0 + 8) * HD + n], bw1[(k0 + 9) * HD + n]);
}

// ---------------- per-graph: start aggregation + ctx MLP + log_z ----------------
__global__ __launch_bounds__(128) void k_graph(
    const float* __restrict__ node, const float* __restrict__ ques,
    const float* __restrict__ ln1g, const float* __restrict__ ln1b,
    const float* __restrict__ zw1,  const float* __restrict__ zb1,
    const float* __restrict__ zw2,  const float* __restrict__ zb2,
    const float* __restrict__ cw1,  const float* __restrict__ cb1,
    const float* __restrict__ cw2,  const float* __restrict__ cb2,
    const int* __restrict__ locals, const int* __restrict__ ptr,
    float* __restrict__ out)
{
    __shared__ float xs[2 * HD];
    __shared__ float hs[HD];
    __shared__ float red[4];
    __shared__ float sc[32];
    __shared__ int   locs[32];

    int g = blockIdx.x, t = threadIdx.x, lane = t & 31, w = t >> 5;
    float q = ques[g * HD + t];
    xs[HD + t] = q;

    int p0 = ptr[g], p1 = ptr[g + 1];
    int cnt = p1 - p0; if (cnt > 32) cnt = 32;

    // warp-parallel scores: warp w handles starts w, w+4, ...
    float4 qv = ld4(ques + g * HD + lane * 4);
    for (int i = w; i < cnt; i += 4){
        int loc = locals[p0 + i];
        float4 nv = ld4(node + (size_t)loc * HD + lane * 4);
        float d = nv.x*qv.x + nv.y*qv.y + nv.z*qv.z + nv.w*qv.w;
        #pragma unroll
        for (int o = 16; o > 0; o >>= 1) d += __shfl_xor_sync(0xFFFFFFFFu, d, o);
        if (lane == 0){ sc[i] = d / SQRT_H; locs[i] = loc; }
    }
    __syncthreads();

    float m = -1e30f;
    for (int i = 0; i < cnt; i++) m = fmaxf(m, sc[i]);
    float den = 0.0f;
    for (int i = 0; i < cnt; i++) den += expf(sc[i] - m);
    float summ = 0.0f;
    for (int i = 0; i < cnt; i++){
        float a = expf(sc[i] - m) / den;
        summ += a * node[(size_t)locs[i] * HD + t];
    }
    xs[t] = summ;
    __syncthreads();

    float acc = cb1[t];
    #pragma unroll 8
    for (int k = 0; k < 2 * HD; k++) acc += xs[k] * cw1[k * HD + t];
    hs[t] = gelu_f(acc);
    __syncthreads();
    float ctx = cb2[t];
    #pragma unroll 8
    for (int k = 0; k < HD; k++) ctx += hs[k] * cw2[k * HD + t];

    float mean = bsum128(ctx, red) * (1.0f / HD);
    float msq  = bsum128(ctx * ctx, red) * (1.0f / HD);
    float rstd = rsqrtf(msq - mean * mean + 1e-5f);
    __syncthreads();
    xs[t] = (ctx - mean) * rstd * ln1g[t] + ln1b[t];
    __syncthreads();
    float a2 = zb1[t];
    #pragma unroll 8
    for (int k = 0; k < HD; k++) a2 += xs[k] * zw1[k * HD + t];
    float h2 = gelu_f(a2);
    float lz = bsum128(h2 * zw2[t], red);
    if (t == 0) out[g * 3 + 0] = lz + zb2[0];
}

// ---------------- edge MLP via bf16 HMMA, B streamed from L2 ----------------
// dyn smem: A[128][392] bf16 (100352) | sBias 512 | sW2 512 | tgt 512 | part 1024
#define OFF_A    0
#define OFF_BIAS 100352
#define OFF_W2   100864
#define OFF_TGT  101376
#define OFF_PART 101888
#define EDGE_SMEM 102912

__global__ __launch_bounds__(256, 2) void k_edge_mma(
    const float* __restrict__ node, const float* __restrict__ ques,
    const float* __restrict__ etok,
    const float* __restrict__ blng, const float* __restrict__ blnb,
    const float* __restrict__ bb1,  const float* __restrict__ bw2,
    const float* __restrict__ bb2,
    const int* __restrict__ ebatch, const int* __restrict__ eidx)
{
    extern __shared__ char sm[];
    __nv_bfloat16* As = (__nv_bfloat16*)(sm + OFF_A);
    float* sBias  = (float*)(sm + OFF_BIAS);
    float* sW2    = (float*)(sm + OFF_W2);
    int*   tgt_s  = (int*)(sm + OFF_TGT);
    float* part   = (float*)(sm + OFF_PART);   // [2][128]

    int t = threadIdx.x, lane = t & 31, w = t >> 5;
    int gid = lane >> 2, tig = lane & 3;
    int e0 = blockIdx.x * TM;

    if (t < HD){ sBias[t] = bb1[t]; sW2[t] = bw2[t]; }

    // ---- lane-parallel index prefetch: lanes 0-15 ebatch, 16-31 eidx[1] ----
    int myidx = 0;
    {
        int ei = e0 + w * 16 + (lane & 15);
        if (ei < ET) myidx = (lane < 16) ? ebatch[ei] : eidx[ET + ei];
        if (lane >= 16 && ei < ET) tgt_s[w * 16 + (lane - 16)] = myidx;
        else if (lane >= 16)       tgt_s[w * 16 + (lane - 16)] = 0;
    }

    // ---- A: gather + LayerNorm(384) -> bf16 row-major padded ----
    #pragma unroll 2
    for (int i = 0; i < 16; i++){
        int el = w * 16 + i;
        int e  = e0 + el;
        int k  = lane * 4;
        __nv_bfloat16* xr = As + el * KP;
        if (e >= ET){
            *(unsigned*)(xr + k) = 0;       *(unsigned*)(xr + k + 2) = 0;
            *(unsigned*)(xr + 128 + k) = 0; *(unsigned*)(xr + 128 + k + 2) = 0;
            *(unsigned*)(xr + 256 + k) = 0; *(unsigned*)(xr + 256 + k + 2) = 0;
            continue;
        }
        int eb = __shfl_sync(0xFFFFFFFFu, myidx, i);
        int tg = __shfl_sync(0xFFFFFFFFu, myidx, 16 + i);
        float4 a = ld4(etok + (size_t)e  * HD + k);
        float4 b = ld4(ques + (size_t)eb * HD + k);
        float4 c = ld4(node + (size_t)tg * HD + k);
        float s  = a.x+a.y+a.z+a.w + b.x+b.y+b.z+b.w + c.x+c.y+c.z+c.w;
        float ss = a.x*a.x+a.y*a.y+a.z*a.z+a.w*a.w
                 + b.x*b.x+b.y*b.y+b.z*b.z+b.w*b.w
                 + c.x*c.x+c.y*c.y+c.z*c.z+c.w*c.w;
        #pragma unroll
        for (int o = 16; o > 0; o >>= 1){
            s  += __shfl_xor_sync(0xFFFFFFFFu, s,  o);
            ss += __shfl_xor_sync(0xFFFFFFFFu, ss, o);
        }
        float mean = s * (1.0f / 384.0f);
        float rstd = rsqrtf(ss * (1.0f / 384.0f) - mean * mean + 1e-5f);
        float4 g0 = ld4(blng + k),       q0 = ld4(blnb + k);
        float4 g1 = ld4(blng + 128 + k), q1 = ld4(blnb + 128 + k);
        float4 g2 = ld4(blng + 256 + k), q2 = ld4(blnb + 256 + k);
        *(unsigned*)(xr + k)           = packbf2((a.x-mean)*rstd*g0.x+q0.x, (a.y-mean)*rstd*g0.y+q0.y);
        *(unsigned*)(xr + k + 2)       = packbf2((a.z-mean)*rstd*g0.z+q0.z, (a.w-mean)*rstd*g0.w+q0.w);
        *(unsigned*)(xr + 128 + k)     = packbf2((b.x-mean)*rstd*g1.x+q1.x, (b.y-mean)*rstd*g1.y+q1.y);
        *(unsigned*)(xr + 128 + k + 2) = packbf2((b.z-mean)*rstd*g1.z+q1.z, (b.w-mean)*rstd*g1.w+q1.w);
        *(unsigned*)(xr + 256 + k)     = packbf2((c.x-mean)*rstd*g2.x+q2.x, (c.y-mean)*rstd*g2.y+q2.y);
        *(unsigned*)(xr + 256 + k + 2) = packbf2((c.z-mean)*rstd*g2.z+q2.z, (c.w-mean)*rstd*g2.w+q2.w);
    }
    __syncthreads();

    // ---- HMMA mainloop: warp tile 32(M) x 64(N); B via LDG.128 from L2 ----
    int mbase = (w & 3) * 32;        // warp's M block
    int qb    = (w >> 2) * 2;        // warp's first quad (of 4)
    int nbt   = qb * 4;              // warp's first n-tile
    float acc[2][8][4];
    #pragma unroll
    for (int mt = 0; mt < 2; mt++)
        #pragma unroll
        for (int j = 0; j < 8; j++)
            #pragma unroll
            for (int r = 0; r < 4; r++) acc[mt][j][r] = 0.0f;

    uint32_t As_u = smem_u32(As);
    int arow = mbase + (lane & 15);
    int acol = (lane >> 4) * 8;
    const uint4* B0 = (const uint4*)g_Bf0 + qb * 32 + lane;
    const uint4* B1 = (const uint4*)g_Bf1 + qb * 32 + lane;

    #pragma unroll 2
    for (int s = 0; s < NKS; s++){
        uint4 u00 = __ldg(B0 + s * 128);        // plane0 tiles nbt..nbt+3
        uint4 u01 = __ldg(B0 + s * 128 + 32);   // plane0 tiles nbt+4..nbt+7
        uint4 u10 = __ldg(B1 + s * 128);
        uint4 u11 = __ldg(B1 + s * 128 + 32);
        uint32_t a0[4], a1[4];
        uint32_t ad = As_u + (uint32_t)((arow * KP + s * 16 + acol) * 2);
        ldm_x4(a0, ad);
        ldm_x4(a1, ad + (uint32_t)(16 * KP * 2));
        mma16816(acc[0][0], a0, u00.x, u10.x);  mma16816(acc[1][0], a1, u00.x, u10.x);
        mma16816(acc[0][1], a0, u00.y, u10.y);  mma16816(acc[1][1], a1, u00.y, u10.y);
        mma16816(acc[0][2], a0, u00.z, u10.z);  mma16816(acc[1][2], a1, u00.z, u10.z);
        mma16816(acc[0][3], a0, u00.w, u10.w);  mma16816(acc[1][3], a1, u00.w, u10.w);
        mma16816(acc[0][4], a0, u01.x, u11.x);  mma16816(acc[1][4], a1, u01.x, u11.x);
        mma16816(acc[0][5], a0, u01.y, u11.y);  mma16816(acc[1][5], a1, u01.y, u11.y);
        mma16816(acc[0][6], a0, u01.z, u11.z);  mma16816(acc[1][6], a1, u01.z, u11.z);
        mma16816(acc[0][7], a0, u01.w, u11.w);  mma16816(acc[1][7], a1, u01.w, u11.w);
    }

    // ---- epilogue: bias + GELU + dot(w2), reduce over lane group ----
    #pragma unroll
    for (int mt = 0; mt < 2; mt++){
        float p0 = 0.0f, p1 = 0.0f;
        #pragma unroll
        for (int j = 0; j < 8; j++){
            int n0 = (nbt + j) * 8 + tig * 2;
            float bia0 = sBias[n0], bia1 = sBias[n0 + 1];
            float w20 = sW2[n0],    w21 = sW2[n0 + 1];
            p0 += gelu_f(acc[mt][j][0] + bia0) * w20 + gelu_f(acc[mt][j][1] + bia1) * w21;
            p1 += gelu_f(acc[mt][j][2] + bia0) * w20 + gelu_f(acc[mt][j][3] + bia1) * w21;
        }
        p0 += __shfl_xor_sync(0xFFFFFFFFu, p0, 1);
        p0 += __shfl_xor_sync(0xFFFFFFFFu, p0, 2);
        p1 += __shfl_xor_sync(0xFFFFFFFFu, p1, 1);
        p1 += __shfl_xor_sync(0xFFFFFFFFu, p1, 2);
        if (tig == 0){
            int r = mbase + mt * 16 + gid;
            part[(w >> 2) * TM + r]     = p0;
            part[(w >> 2) * TM + r + 8] = p1;
        }
    }
    __syncthreads();

    if (w < 4){
        int el = w * 32 + lane;
        int e  = e0 + el;
        if (e < ET){
            float lg = part[el] + part[TM + el] + bb2[0];
            g_logits[e] = lg;
            atomicMax(&g_tmax[tgt_s[el]], fenc(lg));
        }
    }
}

// ---------------- segment softmax passes ----------------
__global__ void k_pass2(const int* __restrict__ eidx){
    int e = blockIdx.x * blockDim.x + threadIdx.x;
    if (e >= ET) return;
    int tg = eidx[ET + e];
    float sh = g_logits[e] - fdec(g_tmax[tg]);
    g_logits[e] = sh;
    atomicAdd(&g_tsum[tg], expf(sh));
}

__global__ void k_pass3(const int* __restrict__ eidx, const int* __restrict__ ebatch,
                        const void* __restrict__ mask){
    int e = blockIdx.x * blockDim.x + threadIdx.x;
    if (e >= ET) return;
    int mode = g_mask_mode;
    int selv;
    if      (mode == 0) selv = ((const unsigned char*)mask)[e] != 0;
    else if (mode == 1) selv = ((const int*)mask)[e] != 0;
    else                selv = ((const float*)mask)[e] != 0.0f;
    if (!selv) return;
    int tg = eidx[ET + e];
    float lp = g_logits[e] - logf(g_tsum[tg]);
    int gb = ebatch[e];
    atomicAdd(&g_logpb[gb], lp);
    atomicAdd(&g_selcnt[gb], 1);
}

// ---------------- final ----------------
__global__ __launch_bounds__(1024) void k_final(float* __restrict__ out){
    __shared__ float rs[32];
    __shared__ int   ri[32];
    int t = threadIdx.x;
    float lp = g_logpb[t];
    int   c  = g_selcnt[t];
    float v = (c > 0) ? -lp : 0.0f;
    int   h = (c > 0) ? 1 : 0;
    #pragma unroll
    for (int o = 16; o > 0; o >>= 1){
        v += __shfl_xor_sync(0xFFFFFFFFu, v, o);
        h += __shfl_xor_sync(0xFFFFFFFFu, h, o);
    }
    if ((t & 31) == 0){ rs[t >> 5] = v; ri[t >> 5] = h; }
    __syncthreads();
    if (t < 32){
        float v2 = rs[t]; int h2 = ri[t];
        #pragma unroll
        for (int o = 16; o > 0; o >>= 1){
            v2 += __shfl_xor_sync(0xFFFFFFFFu, v2, o);
            h2 += __shfl_xor_sync(0xFFFFFFFFu, h2, o);
        }
        if (t == 0){ rs[0] = v2; ri[0] = h2; }
    }
    __syncthreads();
    float pbn = rs[0] / fmaxf((float)ri[0], 1.0f);
    out[t * 3 + 1] = lp;
    out[t * 3 + 2] = pbn;
}

// ---------------- launch ----------------
extern "C" void kernel_launch(void* const* d_in, const int* in_sizes, int n_in,
                              void* d_out, int out_size)
{
    int iN, iQ, iE, iLN1G, iLN1B, iZW1, iZB1, iZW2, iZB2,
        iCW1, iCB1, iCW2, iCB2, iBLG, iBLB, iBW1, iBB1, iBW2, iBB2,
        iLOC, iPTR, iEB, iMASK, iEIDX;
    if (in_sizes[3] == 4096){
        iN=0; iQ=1; iE=2; iLOC=3; iPTR=4; iEB=5; iMASK=6; iEIDX=7;
        iLN1G=8; iLN1B=9; iZW1=10; iZB1=11; iZW2=12; iZB2=13;
        iCW1=14; iCB1=15; iCW2=16; iCB2=17;
        iBLG=18; iBLB=19; iBW1=20; iBB1=21; iBW2=22; iBB2=23;
    } else {
        iN=0; iQ=1; iE=2;
        iLN1G=3; iLN1B=4; iZW1=5; iZB1=6; iZW2=7; iZB2=8;
        iCW1=9; iCB1=10; iCW2=11; iCB2=12;
        iBLG=13; iBLB=14; iBW1=15; iBB1=16; iBW2=17; iBB2=18;
        iLOC=19; iPTR=20; iEB=21; iMASK=22; iEIDX=23;
    }

    const float* node = (const float*)d_in[iN];
    const float* ques = (const float*)d_in[iQ];
    const float* etok = (const float*)d_in[iE];
    const float* ln1g = (const float*)d_in[iLN1G];
    const float* ln1b = (const float*)d_in[iLN1B];
    const float* zw1  = (const float*)d_in[iZW1];
    const float* zb1  = (const float*)d_in[iZB1];
    const float* zw2  = (const float*)d_in[iZW2];
    const float* zb2  = (const float*)d_in[iZB2];
    const float* cw1  = (const float*)d_in[iCW1];
    const float* cb1  = (const float*)d_in[iCB1];
    const float* cw2  = (const float*)d_in[iCW2];
    const float* cb2  = (const float*)d_in[iCB2];
    const float* blng = (const float*)d_in[iBLG];
    const float* blnb = (const float*)d_in[iBLB];
    const float* bw1  = (const float*)d_in[iBW1];
    const float* bb1  = (const float*)d_in[iBB1];
    const float* bw2  = (const float*)d_in[iBW2];
    const float* bb2  = (const float*)d_in[iBB2];
    const int* locals = (const int*)d_in[iLOC];
    const int* ptr    = (const int*)d_in[iPTR];
    const int* ebatch = (const int*)d_in[iEB];
    const void* mask  = (const void*)d_in[iMASK];
    const int* eidx   = (const int*)d_in[iEIDX];
    float* out = (float*)d_out;

    cudaFuncSetAttribute(k_edge_mma, cudaFuncAttributeMaxDynamicSharedMemorySize, EDGE_SMEM);

    k_init<<<(NN + 255) / 256, 256>>>();
    k_detect<<<1, 256>>>((const unsigned*)mask);
    k_bprep<<<(NKS * 16 * 32 + 255) / 256, 256>>>(bw1);
    k_graph<<<NG, 128>>>(node, ques, ln1g, ln1b, zw1, zb1, zw2, zb2,
                         cw1, cb1, cw2, cb2, locals, ptr, out);
    k_edge_mma<<<(ET + TM - 1) / TM, 256, EDGE_SMEM>>>(node, ques, etok, blng, blnb,
                                                       bb1, bw2, bb2, ebatch, eidx);
    k_pass2<<<(ET + 255) / 256, 256>>>(eidx);
    k_pass3<<<(ET + 255) / 256, 256>>>(eidx, ebatch, mask);
    k_final<<<1, 1024>>>(out);
}